// round 15
// baseline (speedup 1.0000x reference)
#include <cuda_runtime.h>
#include <math_constants.h>

// ChamferLoss via exact grid NN. FOUR queries per warp (8 lanes each) for
// Phase A (2x2x2 window). Flagged queries go to a global queue; k_fixup
// resolves each with a 3x3x3 rescan and, if still uncertified, a WARP-WIDE
// BRUTE-FORCE scan of the whole partner structure (worst case hard-capped
// at ~256 coalesced iterations -- no deep-shell serialization).
// d2min(p -> Q) = |p|^2 - 2 * max_j ( p.q_j - 0.5|q_j|^2 )
//
// 16 structures: s in [0,8) nonfiltered (0-3 pn, 4-7 gn, 8192 pts),
//                s in [8,16) filtered (8-11 pf, 12-15 gf, 4096 pts).
// Structure s queries partner s^4.
//
// Exactness: any unscanned point differs by >= 1 cell index beyond a scanned
// face; margins are exact per-axis distances to window/cube faces (infinite
// on domain-clamped sides). Brute force is trivially exact. Rescans are
// harmless: max is idempotent.

#define G     32
#define NCELL (G * G * G)
#define H     0.32f
#define INVH  3.125f
#define RANGE 5.12f
#define NSTRUCT 16
#define CAP   8192

#define NQ_TOTAL 98304
#define QWARPS   8
#define QBLK     (QWARPS * 32)
#define QPB      (QWARPS * 4)            // 32 queries per block
#define QBLOCKS  (NQ_TOTAL / QPB)        // 3072 blocks

#define FIXBLOCKS 512
#define FIXBLK    256

#define FULL 0xffffffffu

__device__ int    g_cnt  [NSTRUCT * NCELL];   // zero at load; re-zeroed by k_scan
__device__ int    g_start[NSTRUCT * NCELL];
__device__ int    g_cur  [NSTRUCT * NCELL];   // after scatter: end of each cell
__device__ float4 g_pts  [NSTRUCT * CAP];
__device__ int    g_qn;                        // fixup queue count
__device__ int    g_qidx[NQ_TOTAL];
__device__ float  g_qm  [NQ_TOTAL];

__device__ __forceinline__ int cell_coord(float x) {
    int c = (int)floorf((x + RANGE) * INVH);
    return min(max(c, 0), G - 1);
}

__device__ __forceinline__ const float* map_point(
    int t, const float* pf, const float* gf, const float* pn, const float* gn,
    int* idx, int* s)
{
    if (t < 65536) {
        const int grp = t >> 13;
        *idx = t & 8191;
        *s   = grp;
        return ((grp < 4) ? pn : gn) + (size_t)(grp & 3) * 8192 * 3;
    } else {
        const int tf  = t - 65536;
        const int grp = tf >> 12;
        *idx = tf & 4095;
        *s   = 8 + grp;
        return ((grp < 4) ? pf : gf) + (size_t)(grp & 3) * 4096 * 3;
    }
}

__global__ __launch_bounds__(256) void k_count(
    const float* __restrict__ pf, const float* __restrict__ gf,
    const float* __restrict__ pn, const float* __restrict__ gn)
{
    const int t = blockIdx.x * 256 + threadIdx.x;
    int i, s;
    const float* P = map_point(t, pf, gf, pn, gn, &i, &s);
    const float x = P[3 * i], y = P[3 * i + 1], z = P[3 * i + 2];
    const int cell = (cell_coord(z) * G + cell_coord(y)) * G + cell_coord(x);
    atomicAdd(&g_cnt[s * NCELL + cell], 1);
}

// Coalesced prefix scan per structure (warp-chunked, nL=1). Zeroes g_cnt/out/qn.
__global__ __launch_bounds__(1024) void k_scan(float* __restrict__ out) {
    const int s    = blockIdx.x;
    const int tid  = threadIdx.x;
    const int lane = tid & 31;
    const int wid  = tid >> 5;
    const int gbase = s * NCELL + wid * 1024;

    if (s == 0 && tid == 0) { out[0] = 0.0f; g_qn = 0; }

    int cnt[32];
    int lane_total = 0;
    #pragma unroll
    for (int k = 0; k < 32; k++) {
        cnt[k] = g_cnt[gbase + k * 32 + lane];
        lane_total += cnt[k];
    }

    int wt = lane_total;
    #pragma unroll
    for (int o = 16; o; o >>= 1) wt += __shfl_xor_sync(FULL, wt, o);

    __shared__ int sh[32];
    if (lane == 0) sh[wid] = wt;
    __syncthreads();
    if (wid == 0) {
        int v = sh[lane];
        int incl = v;
        #pragma unroll
        for (int o = 1; o < 32; o <<= 1) {
            const int t2 = __shfl_up_sync(FULL, incl, o);
            if (lane >= o) incl += t2;
        }
        sh[lane] = incl - v;
    }
    __syncthreads();

    int run = sh[wid];
    #pragma unroll
    for (int k = 0; k < 32; k++) {
        const int c = cnt[k];
        int incl = c;
        #pragma unroll
        for (int o = 1; o < 32; o <<= 1) {
            const int t2 = __shfl_up_sync(FULL, incl, o);
            if (lane >= o) incl += t2;
        }
        const int idx = gbase + k * 32 + lane;
        const int stv = run + incl - c;
        g_start[idx] = stv;
        g_cur[idx]   = stv;
        g_cnt[idx]   = 0;
        run += __shfl_sync(FULL, incl, 31);
    }
}

__global__ __launch_bounds__(256) void k_scatter(
    const float* __restrict__ pf, const float* __restrict__ gf,
    const float* __restrict__ pn, const float* __restrict__ gn)
{
    const int t = blockIdx.x * 256 + threadIdx.x;
    int i, s;
    const float* P = map_point(t, pf, gf, pn, gn, &i, &s);
    const float x = P[3 * i], y = P[3 * i + 1], z = P[3 * i + 2];
    const int cell = (cell_coord(z) * G + cell_coord(y)) * G + cell_coord(x);
    const int slot = atomicAdd(&g_cur[s * NCELL + cell], 1);
    const float nh = -0.5f * fmaf(x, x, fmaf(y, y, z * z));
    g_pts[s * CAP + slot] = make_float4(x, y, z, nh);
}

__device__ __forceinline__ float cube_bound1(
    float px, float py, float pz, int cx, int cy, int cz)
{
    float b = CUDART_INF_F;
    if (cx - 1 > 0)     b = fminf(b, px - (-RANGE + (float)(cx - 1) * H));
    if (cx + 1 < G - 1) b = fminf(b, (-RANGE + (float)(cx + 2) * H) - px);
    if (cy - 1 > 0)     b = fminf(b, py - (-RANGE + (float)(cy - 1) * H));
    if (cy + 1 < G - 1) b = fminf(b, (-RANGE + (float)(cy + 2) * H) - py);
    if (cz - 1 > 0)     b = fminf(b, pz - (-RANGE + (float)(cz - 1) * H));
    if (cz + 1 < G - 1) b = fminf(b, (-RANGE + (float)(cz + 2) * H) - pz);
    return fmaxf(b * 0.9999f, 0.0f);
}

// ---- Phase A: 4 queries per warp; flagged queries go to the fixup queue ----
__global__ __launch_bounds__(QBLK) void k_query(float* __restrict__ out)
{
    const int lane = threadIdx.x & 31;
    const int j    = lane & 7;
    const int qid  = blockIdx.x * QPB + (threadIdx.x >> 3);

    int s_own, u;
    float scale;
    if (qid < 65536) {
        s_own = qid >> 13;
        u     = qid & 8191;
        scale = 0.3f / (4.0f * 8192.0f);
    } else {
        const int tf = qid - 65536;
        s_own = 8 + (tf >> 12);
        u     = tf & 4095;
        scale = 0.7f / (4.0f * 4096.0f);
    }
    const int s = s_own ^ 4;

    const float4 p  = g_pts[s_own * CAP + u];
    const float px = p.x, py = p.y, pz = p.z;
    const float p2 = -2.0f * p.w;

    const float rx = (px + RANGE) * INVH;
    const float ry = (py + RANGE) * INVH;
    const float rz = (pz + RANGE) * INVH;
    const float fx = floorf(rx), fy = floorf(ry), fz = floorf(rz);
    const int cx = min(max((int)fx, 0), G - 1);
    const int cy = min(max((int)fy, 0), G - 1);
    const int cz = min(max((int)fz, 0), G - 1);
    const int lox = min(max((rx - fx >= 0.5f) ? cx : cx - 1, 0), G - 2);
    const int loy = min(max((ry - fy >= 0.5f) ? cy : cy - 1, 0), G - 2);
    const int loz = min(max((rz - fz >= 0.5f) ? cz : cz - 1, 0), G - 2);

    const int*    st  = g_start + s * NCELL;
    const int*    cu  = g_cur   + s * NCELL;
    const float4* pts = g_pts   + s * CAP;

    float m = -CUDART_INF_F;

    {
        const int k  = j & 3;
        const int rb = ((loz + (k >> 1)) * G + (loy + (k & 1))) * G;
        const int rv = (j < 4) ? st[rb + lox] : cu[rb + lox + 1];

        const int endv = __shfl_down_sync(FULL, rv, 4, 8);
        const int cnt  = endv - rv;
        int incl = cnt;
        {
            int t2 = __shfl_up_sync(FULL, incl, 1, 8);
            if (j >= 1) incl += t2;
            t2 = __shfl_up_sync(FULL, incl, 2, 8);
            if (j >= 2) incl += t2;
        }
        const int dl = rv - (incl - cnt);

        const int off1 = __shfl_sync(FULL, incl, 0, 8);
        const int off2 = __shfl_sync(FULL, incl, 1, 8);
        const int off3 = __shfl_sync(FULL, incl, 2, 8);
        const int T    = __shfl_sync(FULL, incl, 3, 8);
        const int dl0  = __shfl_sync(FULL, dl, 0, 8);
        const int dl1  = __shfl_sync(FULL, dl, 1, 8);
        const int dl2  = __shfl_sync(FULL, dl, 2, 8);
        const int dl3  = __shfl_sync(FULL, dl, 3, 8);

        int idx = j;
        for (; idx + 8 < T; idx += 16) {
            {
                const int d = (idx < off2) ? ((idx < off1) ? dl0 : dl1)
                                           : ((idx < off3) ? dl2 : dl3);
                const float4 q = pts[idx + d];
                m = fmaxf(m, fmaf(px, q.x, fmaf(py, q.y, fmaf(pz, q.z, q.w))));
            }
            {
                const int jj = idx + 8;
                const int d = (jj < off2) ? ((jj < off1) ? dl0 : dl1)
                                          : ((jj < off3) ? dl2 : dl3);
                const float4 q = pts[jj + d];
                m = fmaxf(m, fmaf(px, q.x, fmaf(py, q.y, fmaf(pz, q.z, q.w))));
            }
        }
        if (idx < T) {
            const int d = (idx < off2) ? ((idx < off1) ? dl0 : dl1)
                                       : ((idx < off3) ? dl2 : dl3);
            const float4 q = pts[idx + d];
            m = fmaxf(m, fmaf(px, q.x, fmaf(py, q.y, fmaf(pz, q.z, q.w))));
        }
    }
    m = fmaxf(m, __shfl_xor_sync(FULL, m, 4, 8));
    m = fmaxf(m, __shfl_xor_sync(FULL, m, 2, 8));
    m = fmaxf(m, __shfl_xor_sync(FULL, m, 1, 8));
    const float bd2 = fmaf(-2.0f, m, p2);

    float b1 = CUDART_INF_F;
    if (lox > 0)         b1 = fminf(b1, px - (-RANGE + (float)lox * H));
    if (lox + 1 < G - 1) b1 = fminf(b1, (-RANGE + (float)(lox + 2) * H) - px);
    if (loy > 0)         b1 = fminf(b1, py - (-RANGE + (float)loy * H));
    if (loy + 1 < G - 1) b1 = fminf(b1, (-RANGE + (float)(loy + 2) * H) - py);
    if (loz > 0)         b1 = fminf(b1, pz - (-RANGE + (float)loz * H));
    if (loz + 1 < G - 1) b1 = fminf(b1, (-RANGE + (float)(loz + 2) * H) - pz);
    b1 = fmaxf(b1 * 0.9999f, 0.0f);

    const bool needB = bd2 > b1 * b1;     // group-uniform
    float val = 0.0f;
    if (j == 0) {
        if (needB) {
            const int slot = atomicAdd(&g_qn, 1);
            g_qidx[slot] = qid;
            g_qm[slot]   = m;
        } else {
            val = bd2 * scale;
        }
    }
    #pragma unroll
    for (int o = 16; o; o >>= 1)
        val += __shfl_xor_sync(FULL, val, o);

    __shared__ float ws[QWARPS];
    if (lane == 0) ws[threadIdx.x >> 5] = val;
    __syncthreads();
    if (threadIdx.x == 0) {
        float v = 0.0f;
        #pragma unroll
        for (int w = 0; w < QWARPS; w++) v += ws[w];
        atomicAdd(out, v);
    }
}

// ---- fixup: one warp per flagged query; 3x3x3 rescan then brute force ----
__global__ __launch_bounds__(FIXBLK) void k_fixup(float* __restrict__ out)
{
    const int lane   = threadIdx.x & 31;
    const int warpg  = blockIdx.x * (FIXBLK / 32) + (threadIdx.x >> 5);
    const int nwarps = FIXBLOCKS * (FIXBLK / 32);
    const int qn     = g_qn;

    float acc = 0.0f;

    for (int qi = warpg; qi < qn; qi += nwarps) {
        const int qid = g_qidx[qi];
        float m = g_qm[qi];

        int s_own, u, npts;
        float scale;
        if (qid < 65536) {
            s_own = qid >> 13;
            u     = qid & 8191;
            scale = 0.3f / (4.0f * 8192.0f);
            npts  = 8192;
        } else {
            const int tf = qid - 65536;
            s_own = 8 + (tf >> 12);
            u     = tf & 4095;
            scale = 0.7f / (4.0f * 4096.0f);
            npts  = 4096;
        }
        const int s = s_own ^ 4;

        const float4 p  = g_pts[s_own * CAP + u];
        const float px = p.x, py = p.y, pz = p.z;
        const float p2 = -2.0f * p.w;
        const int cx = cell_coord(px), cy = cell_coord(py), cz = cell_coord(pz);

        const int*    st  = g_start + s * NCELL;
        const int*    cu  = g_cur   + s * NCELL;
        const float4* pts = g_pts   + s * CAP;

        // full 3x3x3 rescan (idempotent)
        {
            const int x0 = max(cx - 1, 0), x1 = min(cx + 1, G - 1);
            int beg = 0, end = 0;
            if (lane < 9) {
                const int zz = min(max(cz + lane / 3 - 1, 0), G - 1);
                const int yy = min(max(cy + lane % 3 - 1, 0), G - 1);
                const int rb = (zz * G + yy) * G;
                beg = st[rb + x0];
                end = cu[rb + x1];
            }
            float ml = m;
            #pragma unroll
            for (int k = 0; k < 9; k++) {
                const int b = __shfl_sync(FULL, beg, k);
                const int e = __shfl_sync(FULL, end, k);
                for (int v = b + lane; v < e; v += 32) {
                    const float4 q = pts[v];
                    ml = fmaxf(ml, fmaf(px, q.x, fmaf(py, q.y, fmaf(pz, q.z, q.w))));
                }
            }
            #pragma unroll
            for (int o = 16; o; o >>= 1)
                ml = fmaxf(ml, __shfl_xor_sync(FULL, ml, o));
            m = ml;
        }
        float bd2 = fmaf(-2.0f, m, p2);

        // still uncertified? brute-force the whole structure (coalesced)
        const float b1 = cube_bound1(px, py, pz, cx, cy, cz);
        if (bd2 > b1 * b1) {
            float ml = m;
            for (int v = lane; v < npts; v += 32) {
                const float4 q = pts[v];
                ml = fmaxf(ml, fmaf(px, q.x, fmaf(py, q.y, fmaf(pz, q.z, q.w))));
            }
            #pragma unroll
            for (int o = 16; o; o >>= 1)
                ml = fmaxf(ml, __shfl_xor_sync(FULL, ml, o));
            m = ml;
            bd2 = fmaf(-2.0f, m, p2);
        }

        if (lane == 0) acc += bd2 * scale;
    }

    if (lane == 0 && acc != 0.0f) atomicAdd(out, acc);
}

extern "C" void kernel_launch(void* const* d_in, const int* in_sizes, int n_in,
                              void* d_out, int out_size) {
    const float* pf = (const float*)d_in[0];
    const float* gf = (const float*)d_in[1];
    const float* pn = (const float*)d_in[2];
    const float* gn = (const float*)d_in[3];
    float* out = (float*)d_out;

    // g_cnt zeroed at module load and re-zeroed by k_scan every call.
    k_count<<<NQ_TOTAL / 256, 256>>>(pf, gf, pn, gn);     // launch 0
    k_scan<<<NSTRUCT, 1024>>>(out);                       // launch 1
    k_scatter<<<NQ_TOTAL / 256, 256>>>(pf, gf, pn, gn);   // launch 2
    k_query<<<QBLOCKS, QBLK>>>(out);                      // launch 3 (ncu slot)
    k_fixup<<<FIXBLOCKS, FIXBLK>>>(out);                  // launch 4
}

// round 16
// speedup vs baseline: 1.1374x; 1.1374x over previous
#include <cuda_runtime.h>
#include <math_constants.h>

// ChamferLoss via exact grid NN. FOUR queries per warp (8 lanes each) for
// Phase A (2x2x2 window). Flagged queries go to a global queue; k_fixup does
// a 3x3x3 rescan, then ONE bounded cube scan of provably-sufficient radius
// rq = floor(sqrt(bd2)/H)+1 (rows deduplicated, lane-distributed). Whole-
// structure brute force only for the rare empty-neighborhood queries.
// d2min(p -> Q) = |p|^2 - 2 * max_j ( p.q_j - 0.5|q_j|^2 )
//
// 16 structures: s in [0,8) nonfiltered (0-3 pn, 4-7 gn, 8192 pts),
//                s in [8,16) filtered (8-11 pf, 12-15 gf, 4096 pts).
// Structure s queries partner s^4.
//
// Exactness: cell_coord is monotone and 1-Lipschitz/H in the clamped
// coordinate, so any q with d(p,q) < sqrt(bd2) lies in a cell index within
// rq of p's cell per axis; scanning that cube (union with earlier scans,
// max is idempotent) yields the exact minimum.

#define G     32
#define NCELL (G * G * G)
#define H     0.32f
#define INVH  3.125f
#define RANGE 5.12f
#define NSTRUCT 16
#define CAP   8192

#define NQ_TOTAL 98304
#define QWARPS   8
#define QBLK     (QWARPS * 32)
#define QPB      (QWARPS * 4)            // 32 queries per block
#define QBLOCKS  (NQ_TOTAL / QPB)        // 3072 blocks

#define FIXBLOCKS 512
#define FIXBLK    256

#define FULL 0xffffffffu

__device__ int    g_cnt  [NSTRUCT * NCELL];   // zero at load; re-zeroed by k_scan
__device__ int    g_start[NSTRUCT * NCELL];
__device__ int    g_cur  [NSTRUCT * NCELL];   // after scatter: end of each cell
__device__ float4 g_pts  [NSTRUCT * CAP];
__device__ int    g_qn;                        // fixup queue count
__device__ int    g_qidx[NQ_TOTAL];
__device__ float  g_qm  [NQ_TOTAL];

__device__ __forceinline__ int cell_coord(float x) {
    int c = (int)floorf((x + RANGE) * INVH);
    return min(max(c, 0), G - 1);
}

__device__ __forceinline__ const float* map_point(
    int t, const float* pf, const float* gf, const float* pn, const float* gn,
    int* idx, int* s)
{
    if (t < 65536) {
        const int grp = t >> 13;
        *idx = t & 8191;
        *s   = grp;
        return ((grp < 4) ? pn : gn) + (size_t)(grp & 3) * 8192 * 3;
    } else {
        const int tf  = t - 65536;
        const int grp = tf >> 12;
        *idx = tf & 4095;
        *s   = 8 + grp;
        return ((grp < 4) ? pf : gf) + (size_t)(grp & 3) * 4096 * 3;
    }
}

__global__ __launch_bounds__(256) void k_count(
    const float* __restrict__ pf, const float* __restrict__ gf,
    const float* __restrict__ pn, const float* __restrict__ gn)
{
    const int t = blockIdx.x * 256 + threadIdx.x;
    int i, s;
    const float* P = map_point(t, pf, gf, pn, gn, &i, &s);
    const float x = P[3 * i], y = P[3 * i + 1], z = P[3 * i + 2];
    const int cell = (cell_coord(z) * G + cell_coord(y)) * G + cell_coord(x);
    atomicAdd(&g_cnt[s * NCELL + cell], 1);
}

// Coalesced prefix scan per structure (warp-chunked, nL=1). Zeroes g_cnt/out/qn.
__global__ __launch_bounds__(1024) void k_scan(float* __restrict__ out) {
    const int s    = blockIdx.x;
    const int tid  = threadIdx.x;
    const int lane = tid & 31;
    const int wid  = tid >> 5;
    const int gbase = s * NCELL + wid * 1024;

    if (s == 0 && tid == 0) { out[0] = 0.0f; g_qn = 0; }

    int cnt[32];
    int lane_total = 0;
    #pragma unroll
    for (int k = 0; k < 32; k++) {
        cnt[k] = g_cnt[gbase + k * 32 + lane];
        lane_total += cnt[k];
    }

    int wt = lane_total;
    #pragma unroll
    for (int o = 16; o; o >>= 1) wt += __shfl_xor_sync(FULL, wt, o);

    __shared__ int sh[32];
    if (lane == 0) sh[wid] = wt;
    __syncthreads();
    if (wid == 0) {
        int v = sh[lane];
        int incl = v;
        #pragma unroll
        for (int o = 1; o < 32; o <<= 1) {
            const int t2 = __shfl_up_sync(FULL, incl, o);
            if (lane >= o) incl += t2;
        }
        sh[lane] = incl - v;
    }
    __syncthreads();

    int run = sh[wid];
    #pragma unroll
    for (int k = 0; k < 32; k++) {
        const int c = cnt[k];
        int incl = c;
        #pragma unroll
        for (int o = 1; o < 32; o <<= 1) {
            const int t2 = __shfl_up_sync(FULL, incl, o);
            if (lane >= o) incl += t2;
        }
        const int idx = gbase + k * 32 + lane;
        const int stv = run + incl - c;
        g_start[idx] = stv;
        g_cur[idx]   = stv;
        g_cnt[idx]   = 0;
        run += __shfl_sync(FULL, incl, 31);
    }
}

__global__ __launch_bounds__(256) void k_scatter(
    const float* __restrict__ pf, const float* __restrict__ gf,
    const float* __restrict__ pn, const float* __restrict__ gn)
{
    const int t = blockIdx.x * 256 + threadIdx.x;
    int i, s;
    const float* P = map_point(t, pf, gf, pn, gn, &i, &s);
    const float x = P[3 * i], y = P[3 * i + 1], z = P[3 * i + 2];
    const int cell = (cell_coord(z) * G + cell_coord(y)) * G + cell_coord(x);
    const int slot = atomicAdd(&g_cur[s * NCELL + cell], 1);
    const float nh = -0.5f * fmaf(x, x, fmaf(y, y, z * z));
    g_pts[s * CAP + slot] = make_float4(x, y, z, nh);
}

// ---- Phase A: 4 queries per warp; flagged queries go to the fixup queue ----
__global__ __launch_bounds__(QBLK) void k_query(float* __restrict__ out)
{
    const int lane = threadIdx.x & 31;
    const int j    = lane & 7;
    const int qid  = blockIdx.x * QPB + (threadIdx.x >> 3);

    int s_own, u;
    float scale;
    if (qid < 65536) {
        s_own = qid >> 13;
        u     = qid & 8191;
        scale = 0.3f / (4.0f * 8192.0f);
    } else {
        const int tf = qid - 65536;
        s_own = 8 + (tf >> 12);
        u     = tf & 4095;
        scale = 0.7f / (4.0f * 4096.0f);
    }
    const int s = s_own ^ 4;

    const float4 p  = g_pts[s_own * CAP + u];
    const float px = p.x, py = p.y, pz = p.z;
    const float p2 = -2.0f * p.w;

    const float rx = (px + RANGE) * INVH;
    const float ry = (py + RANGE) * INVH;
    const float rz = (pz + RANGE) * INVH;
    const float fx = floorf(rx), fy = floorf(ry), fz = floorf(rz);
    const int cx = min(max((int)fx, 0), G - 1);
    const int cy = min(max((int)fy, 0), G - 1);
    const int cz = min(max((int)fz, 0), G - 1);
    const int lox = min(max((rx - fx >= 0.5f) ? cx : cx - 1, 0), G - 2);
    const int loy = min(max((ry - fy >= 0.5f) ? cy : cy - 1, 0), G - 2);
    const int loz = min(max((rz - fz >= 0.5f) ? cz : cz - 1, 0), G - 2);

    const int*    st  = g_start + s * NCELL;
    const int*    cu  = g_cur   + s * NCELL;
    const float4* pts = g_pts   + s * CAP;

    float m = -CUDART_INF_F;

    {
        const int k  = j & 3;
        const int rb = ((loz + (k >> 1)) * G + (loy + (k & 1))) * G;
        const int rv = (j < 4) ? st[rb + lox] : cu[rb + lox + 1];

        const int endv = __shfl_down_sync(FULL, rv, 4, 8);
        const int cnt  = endv - rv;
        int incl = cnt;
        {
            int t2 = __shfl_up_sync(FULL, incl, 1, 8);
            if (j >= 1) incl += t2;
            t2 = __shfl_up_sync(FULL, incl, 2, 8);
            if (j >= 2) incl += t2;
        }
        const int dl = rv - (incl - cnt);

        const int off1 = __shfl_sync(FULL, incl, 0, 8);
        const int off2 = __shfl_sync(FULL, incl, 1, 8);
        const int off3 = __shfl_sync(FULL, incl, 2, 8);
        const int T    = __shfl_sync(FULL, incl, 3, 8);
        const int dl0  = __shfl_sync(FULL, dl, 0, 8);
        const int dl1  = __shfl_sync(FULL, dl, 1, 8);
        const int dl2  = __shfl_sync(FULL, dl, 2, 8);
        const int dl3  = __shfl_sync(FULL, dl, 3, 8);

        int idx = j;
        for (; idx + 8 < T; idx += 16) {
            {
                const int d = (idx < off2) ? ((idx < off1) ? dl0 : dl1)
                                           : ((idx < off3) ? dl2 : dl3);
                const float4 q = pts[idx + d];
                m = fmaxf(m, fmaf(px, q.x, fmaf(py, q.y, fmaf(pz, q.z, q.w))));
            }
            {
                const int jj = idx + 8;
                const int d = (jj < off2) ? ((jj < off1) ? dl0 : dl1)
                                          : ((jj < off3) ? dl2 : dl3);
                const float4 q = pts[jj + d];
                m = fmaxf(m, fmaf(px, q.x, fmaf(py, q.y, fmaf(pz, q.z, q.w))));
            }
        }
        if (idx < T) {
            const int d = (idx < off2) ? ((idx < off1) ? dl0 : dl1)
                                       : ((idx < off3) ? dl2 : dl3);
            const float4 q = pts[idx + d];
            m = fmaxf(m, fmaf(px, q.x, fmaf(py, q.y, fmaf(pz, q.z, q.w))));
        }
    }
    m = fmaxf(m, __shfl_xor_sync(FULL, m, 4, 8));
    m = fmaxf(m, __shfl_xor_sync(FULL, m, 2, 8));
    m = fmaxf(m, __shfl_xor_sync(FULL, m, 1, 8));
    const float bd2 = fmaf(-2.0f, m, p2);

    float b1 = CUDART_INF_F;
    if (lox > 0)         b1 = fminf(b1, px - (-RANGE + (float)lox * H));
    if (lox + 1 < G - 1) b1 = fminf(b1, (-RANGE + (float)(lox + 2) * H) - px);
    if (loy > 0)         b1 = fminf(b1, py - (-RANGE + (float)loy * H));
    if (loy + 1 < G - 1) b1 = fminf(b1, (-RANGE + (float)(loy + 2) * H) - py);
    if (loz > 0)         b1 = fminf(b1, pz - (-RANGE + (float)loz * H));
    if (loz + 1 < G - 1) b1 = fminf(b1, (-RANGE + (float)(loz + 2) * H) - pz);
    b1 = fmaxf(b1 * 0.9999f, 0.0f);

    const bool needB = bd2 > b1 * b1;     // group-uniform
    float val = 0.0f;
    if (j == 0) {
        if (needB) {
            const int slot = atomicAdd(&g_qn, 1);
            g_qidx[slot] = qid;
            g_qm[slot]   = m;
        } else {
            val = bd2 * scale;
        }
    }
    #pragma unroll
    for (int o = 16; o; o >>= 1)
        val += __shfl_xor_sync(FULL, val, o);

    __shared__ float ws[QWARPS];
    if (lane == 0) ws[threadIdx.x >> 5] = val;
    __syncthreads();
    if (threadIdx.x == 0) {
        float v = 0.0f;
        #pragma unroll
        for (int w = 0; w < QWARPS; w++) v += ws[w];
        atomicAdd(out, v);
    }
}

// ---- fixup: warp per flagged query; 3x3x3 rescan, then ONE bounded cube ----
__global__ __launch_bounds__(FIXBLK) void k_fixup(float* __restrict__ out)
{
    const int lane   = threadIdx.x & 31;
    const int warpg  = blockIdx.x * (FIXBLK / 32) + (threadIdx.x >> 5);
    const int nwarps = FIXBLOCKS * (FIXBLK / 32);
    const int qn     = g_qn;

    float acc = 0.0f;

    for (int qi = warpg; qi < qn; qi += nwarps) {
        const int qid = g_qidx[qi];
        float m = g_qm[qi];

        int s_own, u, npts;
        float scale;
        if (qid < 65536) {
            s_own = qid >> 13;
            u     = qid & 8191;
            scale = 0.3f / (4.0f * 8192.0f);
            npts  = 8192;
        } else {
            const int tf = qid - 65536;
            s_own = 8 + (tf >> 12);
            u     = tf & 4095;
            scale = 0.7f / (4.0f * 4096.0f);
            npts  = 4096;
        }
        const int s = s_own ^ 4;

        const float4 p  = g_pts[s_own * CAP + u];
        const float px = p.x, py = p.y, pz = p.z;
        const float p2 = -2.0f * p.w;
        const int cx = cell_coord(px), cy = cell_coord(py), cz = cell_coord(pz);

        const int*    st  = g_start + s * NCELL;
        const int*    cu  = g_cur   + s * NCELL;
        const float4* pts = g_pts   + s * CAP;

        // full 3x3x3 rescan (idempotent)
        {
            const int x0 = max(cx - 1, 0), x1 = min(cx + 1, G - 1);
            int beg = 0, end = 0;
            if (lane < 9) {
                const int zz = min(max(cz + lane / 3 - 1, 0), G - 1);
                const int yy = min(max(cy + lane % 3 - 1, 0), G - 1);
                const int rb = (zz * G + yy) * G;
                beg = st[rb + x0];
                end = cu[rb + x1];
            }
            float ml = m;
            #pragma unroll
            for (int k = 0; k < 9; k++) {
                const int b = __shfl_sync(FULL, beg, k);
                const int e = __shfl_sync(FULL, end, k);
                for (int v = b + lane; v < e; v += 32) {
                    const float4 q = pts[v];
                    ml = fmaxf(ml, fmaf(px, q.x, fmaf(py, q.y, fmaf(pz, q.z, q.w))));
                }
            }
            #pragma unroll
            for (int o = 16; o; o >>= 1)
                ml = fmaxf(ml, __shfl_xor_sync(FULL, ml, o));
            m = ml;
        }
        float bd2 = fmaf(-2.0f, m, p2);

        // certification margin of the r=1 cube (inf on domain-clamped sides)
        float b1 = CUDART_INF_F;
        if (cx - 1 > 0)     b1 = fminf(b1, px - (-RANGE + (float)(cx - 1) * H));
        if (cx + 1 < G - 1) b1 = fminf(b1, (-RANGE + (float)(cx + 2) * H) - px);
        if (cy - 1 > 0)     b1 = fminf(b1, py - (-RANGE + (float)(cy - 1) * H));
        if (cy + 1 < G - 1) b1 = fminf(b1, (-RANGE + (float)(cy + 2) * H) - py);
        if (cz - 1 > 0)     b1 = fminf(b1, pz - (-RANGE + (float)(cz - 1) * H));
        if (cz + 1 < G - 1) b1 = fminf(b1, (-RANGE + (float)(cz + 2) * H) - pz);
        b1 = fmaxf(b1 * 0.9999f, 0.0f);

        if (bd2 > b1 * b1) {
            // radius that provably contains any improving point
            const int rq = (bd2 < 4.0f) ? ((int)(sqrtf(bd2) * INVH) + 1) : G;

            if (rq >= 8) {
                // rare: brute-force whole structure (coalesced)
                float ml = m;
                for (int v = lane; v < npts; v += 32) {
                    const float4 q = pts[v];
                    ml = fmaxf(ml, fmaf(px, q.x, fmaf(py, q.y, fmaf(pz, q.z, q.w))));
                }
                #pragma unroll
                for (int o = 16; o; o >>= 1)
                    ml = fmaxf(ml, __shfl_xor_sync(FULL, ml, o));
                m = ml;
            } else {
                // ONE bounded cube scan: valid rows only, lane-distributed
                const int z0 = max(cz - rq, 0), z1 = min(cz + rq, G - 1);
                const int y0 = max(cy - rq, 0), y1 = min(cy + rq, G - 1);
                const int x0 = max(cx - rq, 0), x1 = min(cx + rq, G - 1);
                const int ny = y1 - y0 + 1;
                const int nr = (z1 - z0 + 1) * ny;
                float ml = m;
                for (int ridx = lane; ridx < nr; ridx += 32) {
                    const int zz = z0 + ridx / ny;
                    const int yy = y0 + ridx % ny;
                    const int rb = (zz * G + yy) * G;
                    const int bb = st[rb + x0], ee = cu[rb + x1];
                    for (int v = bb; v < ee; v++) {
                        const float4 q = pts[v];
                        ml = fmaxf(ml, fmaf(px, q.x, fmaf(py, q.y, fmaf(pz, q.z, q.w))));
                    }
                }
                #pragma unroll
                for (int o = 16; o; o >>= 1)
                    ml = fmaxf(ml, __shfl_xor_sync(FULL, ml, o));
                m = ml;
            }
            bd2 = fmaf(-2.0f, m, p2);
        }

        if (lane == 0) acc += bd2 * scale;
    }

    if (lane == 0 && acc != 0.0f) atomicAdd(out, acc);
}

extern "C" void kernel_launch(void* const* d_in, const int* in_sizes, int n_in,
                              void* d_out, int out_size) {
    const float* pf = (const float*)d_in[0];
    const float* gf = (const float*)d_in[1];
    const float* pn = (const float*)d_in[2];
    const float* gn = (const float*)d_in[3];
    float* out = (float*)d_out;

    // g_cnt zeroed at module load and re-zeroed by k_scan every call.
    k_count<<<NQ_TOTAL / 256, 256>>>(pf, gf, pn, gn);     // launch 0
    k_scan<<<NSTRUCT, 1024>>>(out);                       // launch 1
    k_scatter<<<NQ_TOTAL / 256, 256>>>(pf, gf, pn, gn);   // launch 2
    k_query<<<QBLOCKS, QBLK>>>(out);                      // launch 3 (ncu slot)
    k_fixup<<<FIXBLOCKS, FIXBLK>>>(out);                  // launch 4
}

// round 17
// speedup vs baseline: 1.3678x; 1.2026x over previous
#include <cuda_runtime.h>
#include <math_constants.h>

// ChamferLoss via exact grid NN. FOUR queries per warp (8 lanes each) for
// Phase A (2x2x2 window). Flagged queries go to a global queue; k_fixup does
// a FLATTENED 3x3x3 rescan (9 rows -> one union index space, full MLP), then
// ONE bounded cube scan of provably-sufficient radius rq = floor(sqrt(bd2)/H)+1.
// d2min(p -> Q) = |p|^2 - 2 * max_j ( p.q_j - 0.5|q_j|^2 )
//
// 16 structures: s in [0,8) nonfiltered (0-3 pn, 4-7 gn, 8192 pts),
//                s in [8,16) filtered (8-11 pf, 12-15 gf, 4096 pts).
// Structure s queries partner s^4.
//
// Exactness: cell_coord is monotone and 1-Lipschitz/H in the clamped
// coordinate, so any q with d(p,q) < sqrt(bd2) lies within rq cells of p's
// cell per axis; scanning that cube (union with earlier scans, max is
// idempotent) yields the exact minimum.

#define G     32
#define NCELL (G * G * G)
#define H     0.32f
#define INVH  3.125f
#define RANGE 5.12f
#define NSTRUCT 16
#define CAP   8192

#define NQ_TOTAL 98304
#define QWARPS   8
#define QBLK     (QWARPS * 32)
#define QPB      (QWARPS * 4)            // 32 queries per block
#define QBLOCKS  (NQ_TOTAL / QPB)        // 3072 blocks

#define FIXBLOCKS 512
#define FIXBLK    256

#define FULL 0xffffffffu

__device__ int    g_cnt  [NSTRUCT * NCELL];   // zero at load; re-zeroed by k_scan
__device__ int    g_start[NSTRUCT * NCELL];
__device__ int    g_cur  [NSTRUCT * NCELL];   // after scatter: end of each cell
__device__ float4 g_pts  [NSTRUCT * CAP];
__device__ int    g_qn;                        // fixup queue count
__device__ int    g_qidx[NQ_TOTAL];
__device__ float  g_qm  [NQ_TOTAL];

__device__ __forceinline__ int cell_coord(float x) {
    int c = (int)floorf((x + RANGE) * INVH);
    return min(max(c, 0), G - 1);
}

__device__ __forceinline__ const float* map_point(
    int t, const float* pf, const float* gf, const float* pn, const float* gn,
    int* idx, int* s)
{
    if (t < 65536) {
        const int grp = t >> 13;
        *idx = t & 8191;
        *s   = grp;
        return ((grp < 4) ? pn : gn) + (size_t)(grp & 3) * 8192 * 3;
    } else {
        const int tf  = t - 65536;
        const int grp = tf >> 12;
        *idx = tf & 4095;
        *s   = 8 + grp;
        return ((grp < 4) ? pf : gf) + (size_t)(grp & 3) * 4096 * 3;
    }
}

__global__ __launch_bounds__(256) void k_count(
    const float* __restrict__ pf, const float* __restrict__ gf,
    const float* __restrict__ pn, const float* __restrict__ gn)
{
    const int t = blockIdx.x * 256 + threadIdx.x;
    int i, s;
    const float* P = map_point(t, pf, gf, pn, gn, &i, &s);
    const float x = P[3 * i], y = P[3 * i + 1], z = P[3 * i + 2];
    const int cell = (cell_coord(z) * G + cell_coord(y)) * G + cell_coord(x);
    atomicAdd(&g_cnt[s * NCELL + cell], 1);
}

// Coalesced prefix scan per structure (warp-chunked, nL=1). Zeroes g_cnt/out/qn.
__global__ __launch_bounds__(1024) void k_scan(float* __restrict__ out) {
    const int s    = blockIdx.x;
    const int tid  = threadIdx.x;
    const int lane = tid & 31;
    const int wid  = tid >> 5;
    const int gbase = s * NCELL + wid * 1024;

    if (s == 0 && tid == 0) { out[0] = 0.0f; g_qn = 0; }

    int cnt[32];
    int lane_total = 0;
    #pragma unroll
    for (int k = 0; k < 32; k++) {
        cnt[k] = g_cnt[gbase + k * 32 + lane];
        lane_total += cnt[k];
    }

    int wt = lane_total;
    #pragma unroll
    for (int o = 16; o; o >>= 1) wt += __shfl_xor_sync(FULL, wt, o);

    __shared__ int sh[32];
    if (lane == 0) sh[wid] = wt;
    __syncthreads();
    if (wid == 0) {
        int v = sh[lane];
        int incl = v;
        #pragma unroll
        for (int o = 1; o < 32; o <<= 1) {
            const int t2 = __shfl_up_sync(FULL, incl, o);
            if (lane >= o) incl += t2;
        }
        sh[lane] = incl - v;
    }
    __syncthreads();

    int run = sh[wid];
    #pragma unroll
    for (int k = 0; k < 32; k++) {
        const int c = cnt[k];
        int incl = c;
        #pragma unroll
        for (int o = 1; o < 32; o <<= 1) {
            const int t2 = __shfl_up_sync(FULL, incl, o);
            if (lane >= o) incl += t2;
        }
        const int idx = gbase + k * 32 + lane;
        const int stv = run + incl - c;
        g_start[idx] = stv;
        g_cur[idx]   = stv;
        g_cnt[idx]   = 0;
        run += __shfl_sync(FULL, incl, 31);
    }
}

__global__ __launch_bounds__(256) void k_scatter(
    const float* __restrict__ pf, const float* __restrict__ gf,
    const float* __restrict__ pn, const float* __restrict__ gn)
{
    const int t = blockIdx.x * 256 + threadIdx.x;
    int i, s;
    const float* P = map_point(t, pf, gf, pn, gn, &i, &s);
    const float x = P[3 * i], y = P[3 * i + 1], z = P[3 * i + 2];
    const int cell = (cell_coord(z) * G + cell_coord(y)) * G + cell_coord(x);
    const int slot = atomicAdd(&g_cur[s * NCELL + cell], 1);
    const float nh = -0.5f * fmaf(x, x, fmaf(y, y, z * z));
    g_pts[s * CAP + slot] = make_float4(x, y, z, nh);
}

// ---- Phase A: 4 queries per warp; flagged queries go to the fixup queue ----
__global__ __launch_bounds__(QBLK) void k_query(float* __restrict__ out)
{
    const int lane = threadIdx.x & 31;
    const int j    = lane & 7;
    const int qid  = blockIdx.x * QPB + (threadIdx.x >> 3);

    int s_own, u;
    float scale;
    if (qid < 65536) {
        s_own = qid >> 13;
        u     = qid & 8191;
        scale = 0.3f / (4.0f * 8192.0f);
    } else {
        const int tf = qid - 65536;
        s_own = 8 + (tf >> 12);
        u     = tf & 4095;
        scale = 0.7f / (4.0f * 4096.0f);
    }
    const int s = s_own ^ 4;

    const float4 p  = g_pts[s_own * CAP + u];
    const float px = p.x, py = p.y, pz = p.z;
    const float p2 = -2.0f * p.w;

    const float rx = (px + RANGE) * INVH;
    const float ry = (py + RANGE) * INVH;
    const float rz = (pz + RANGE) * INVH;
    const float fx = floorf(rx), fy = floorf(ry), fz = floorf(rz);
    const int cx = min(max((int)fx, 0), G - 1);
    const int cy = min(max((int)fy, 0), G - 1);
    const int cz = min(max((int)fz, 0), G - 1);
    const int lox = min(max((rx - fx >= 0.5f) ? cx : cx - 1, 0), G - 2);
    const int loy = min(max((ry - fy >= 0.5f) ? cy : cy - 1, 0), G - 2);
    const int loz = min(max((rz - fz >= 0.5f) ? cz : cz - 1, 0), G - 2);

    const int*    st  = g_start + s * NCELL;
    const int*    cu  = g_cur   + s * NCELL;
    const float4* pts = g_pts   + s * CAP;

    float m = -CUDART_INF_F;

    {
        const int k  = j & 3;
        const int rb = ((loz + (k >> 1)) * G + (loy + (k & 1))) * G;
        const int rv = (j < 4) ? st[rb + lox] : cu[rb + lox + 1];

        const int endv = __shfl_down_sync(FULL, rv, 4, 8);
        const int cnt  = endv - rv;
        int incl = cnt;
        {
            int t2 = __shfl_up_sync(FULL, incl, 1, 8);
            if (j >= 1) incl += t2;
            t2 = __shfl_up_sync(FULL, incl, 2, 8);
            if (j >= 2) incl += t2;
        }
        const int dl = rv - (incl - cnt);

        const int off1 = __shfl_sync(FULL, incl, 0, 8);
        const int off2 = __shfl_sync(FULL, incl, 1, 8);
        const int off3 = __shfl_sync(FULL, incl, 2, 8);
        const int T    = __shfl_sync(FULL, incl, 3, 8);
        const int dl0  = __shfl_sync(FULL, dl, 0, 8);
        const int dl1  = __shfl_sync(FULL, dl, 1, 8);
        const int dl2  = __shfl_sync(FULL, dl, 2, 8);
        const int dl3  = __shfl_sync(FULL, dl, 3, 8);

        int idx = j;
        for (; idx + 8 < T; idx += 16) {
            {
                const int d = (idx < off2) ? ((idx < off1) ? dl0 : dl1)
                                           : ((idx < off3) ? dl2 : dl3);
                const float4 q = pts[idx + d];
                m = fmaxf(m, fmaf(px, q.x, fmaf(py, q.y, fmaf(pz, q.z, q.w))));
            }
            {
                const int jj = idx + 8;
                const int d = (jj < off2) ? ((jj < off1) ? dl0 : dl1)
                                          : ((jj < off3) ? dl2 : dl3);
                const float4 q = pts[jj + d];
                m = fmaxf(m, fmaf(px, q.x, fmaf(py, q.y, fmaf(pz, q.z, q.w))));
            }
        }
        if (idx < T) {
            const int d = (idx < off2) ? ((idx < off1) ? dl0 : dl1)
                                       : ((idx < off3) ? dl2 : dl3);
            const float4 q = pts[idx + d];
            m = fmaxf(m, fmaf(px, q.x, fmaf(py, q.y, fmaf(pz, q.z, q.w))));
        }
    }
    m = fmaxf(m, __shfl_xor_sync(FULL, m, 4, 8));
    m = fmaxf(m, __shfl_xor_sync(FULL, m, 2, 8));
    m = fmaxf(m, __shfl_xor_sync(FULL, m, 1, 8));
    const float bd2 = fmaf(-2.0f, m, p2);

    float b1 = CUDART_INF_F;
    if (lox > 0)         b1 = fminf(b1, px - (-RANGE + (float)lox * H));
    if (lox + 1 < G - 1) b1 = fminf(b1, (-RANGE + (float)(lox + 2) * H) - px);
    if (loy > 0)         b1 = fminf(b1, py - (-RANGE + (float)loy * H));
    if (loy + 1 < G - 1) b1 = fminf(b1, (-RANGE + (float)(loy + 2) * H) - py);
    if (loz > 0)         b1 = fminf(b1, pz - (-RANGE + (float)loz * H));
    if (loz + 1 < G - 1) b1 = fminf(b1, (-RANGE + (float)(loz + 2) * H) - pz);
    b1 = fmaxf(b1 * 0.9999f, 0.0f);

    const bool needB = bd2 > b1 * b1;     // group-uniform
    float val = 0.0f;
    if (j == 0) {
        if (needB) {
            const int slot = atomicAdd(&g_qn, 1);
            g_qidx[slot] = qid;
            g_qm[slot]   = m;
        } else {
            val = bd2 * scale;
        }
    }
    #pragma unroll
    for (int o = 16; o; o >>= 1)
        val += __shfl_xor_sync(FULL, val, o);

    __shared__ float ws[QWARPS];
    if (lane == 0) ws[threadIdx.x >> 5] = val;
    __syncthreads();
    if (threadIdx.x == 0) {
        float v = 0.0f;
        #pragma unroll
        for (int w = 0; w < QWARPS; w++) v += ws[w];
        atomicAdd(out, v);
    }
}

// ---- fixup: warp per flagged query; FLAT 3x3x3 rescan + one bounded cube ----
__global__ __launch_bounds__(FIXBLK) void k_fixup(float* __restrict__ out)
{
    const int lane   = threadIdx.x & 31;
    const int warpg  = blockIdx.x * (FIXBLK / 32) + (threadIdx.x >> 5);
    const int nwarps = FIXBLOCKS * (FIXBLK / 32);
    const int qn     = g_qn;

    float acc = 0.0f;

    for (int qi = warpg; qi < qn; qi += nwarps) {
        const int qid = g_qidx[qi];
        float m = g_qm[qi];

        int s_own, u, npts;
        float scale;
        if (qid < 65536) {
            s_own = qid >> 13;
            u     = qid & 8191;
            scale = 0.3f / (4.0f * 8192.0f);
            npts  = 8192;
        } else {
            const int tf = qid - 65536;
            s_own = 8 + (tf >> 12);
            u     = tf & 4095;
            scale = 0.7f / (4.0f * 4096.0f);
            npts  = 4096;
        }
        const int s = s_own ^ 4;

        const float4 p  = g_pts[s_own * CAP + u];
        const float px = p.x, py = p.y, pz = p.z;
        const float p2 = -2.0f * p.w;
        const int cx = cell_coord(px), cy = cell_coord(py), cz = cell_coord(pz);

        const int*    st  = g_start + s * NCELL;
        const int*    cu  = g_cur   + s * NCELL;
        const float4* pts = g_pts   + s * CAP;

        // ---- FLATTENED 3x3x3 rescan: 9 rows -> one union index space ----
        {
            const int x0 = max(cx - 1, 0), x1 = min(cx + 1, G - 1);
            int beg = 0, end = 0;
            if (lane < 9) {
                const int zz = min(max(cz + lane / 3 - 1, 0), G - 1);
                const int yy = min(max(cy + lane % 3 - 1, 0), G - 1);
                const int rb = (zz * G + yy) * G;
                beg = st[rb + x0];
                end = cu[rb + x1];
            }
            const int cnt = end - beg;              // 0 for lane >= 9
            int incl = cnt;
            #pragma unroll
            for (int o = 1; o < 16; o <<= 1) {
                const int t2 = __shfl_up_sync(FULL, incl, o);
                if (lane >= o) incl += t2;
            }
            const int dl = beg - (incl - cnt);      // valid on lanes 0-8

            const int T    = __shfl_sync(FULL, incl, 8);
            const int off1 = __shfl_sync(FULL, incl, 0);
            const int off2 = __shfl_sync(FULL, incl, 1);
            const int off3 = __shfl_sync(FULL, incl, 2);
            const int off4 = __shfl_sync(FULL, incl, 3);
            const int off5 = __shfl_sync(FULL, incl, 4);
            const int off6 = __shfl_sync(FULL, incl, 5);
            const int off7 = __shfl_sync(FULL, incl, 6);
            const int off8 = __shfl_sync(FULL, incl, 7);
            const int dl0  = __shfl_sync(FULL, dl, 0);
            const int dl1  = __shfl_sync(FULL, dl, 1);
            const int dl2  = __shfl_sync(FULL, dl, 2);
            const int dl3  = __shfl_sync(FULL, dl, 3);
            const int dl4  = __shfl_sync(FULL, dl, 4);
            const int dl5  = __shfl_sync(FULL, dl, 5);
            const int dl6  = __shfl_sync(FULL, dl, 6);
            const int dl7  = __shfl_sync(FULL, dl, 7);
            const int dl8  = __shfl_sync(FULL, dl, 8);

            float ml = m;
            for (int idx = lane; idx < T; idx += 32) {
                int d = dl0;
                d = (idx >= off1) ? dl1 : d;
                d = (idx >= off2) ? dl2 : d;
                d = (idx >= off3) ? dl3 : d;
                d = (idx >= off4) ? dl4 : d;
                d = (idx >= off5) ? dl5 : d;
                d = (idx >= off6) ? dl6 : d;
                d = (idx >= off7) ? dl7 : d;
                d = (idx >= off8) ? dl8 : d;
                const float4 q = pts[idx + d];
                ml = fmaxf(ml, fmaf(px, q.x, fmaf(py, q.y, fmaf(pz, q.z, q.w))));
            }
            #pragma unroll
            for (int o = 16; o; o >>= 1)
                ml = fmaxf(ml, __shfl_xor_sync(FULL, ml, o));
            m = ml;
        }
        float bd2 = fmaf(-2.0f, m, p2);

        // certification margin of the r=1 cube (inf on domain-clamped sides)
        float b1 = CUDART_INF_F;
        if (cx - 1 > 0)     b1 = fminf(b1, px - (-RANGE + (float)(cx - 1) * H));
        if (cx + 1 < G - 1) b1 = fminf(b1, (-RANGE + (float)(cx + 2) * H) - px);
        if (cy - 1 > 0)     b1 = fminf(b1, py - (-RANGE + (float)(cy - 1) * H));
        if (cy + 1 < G - 1) b1 = fminf(b1, (-RANGE + (float)(cy + 2) * H) - py);
        if (cz - 1 > 0)     b1 = fminf(b1, pz - (-RANGE + (float)(cz - 1) * H));
        if (cz + 1 < G - 1) b1 = fminf(b1, (-RANGE + (float)(cz + 2) * H) - pz);
        b1 = fmaxf(b1 * 0.9999f, 0.0f);

        if (bd2 > b1 * b1) {
            const int rq = (bd2 < 4.0f) ? ((int)(sqrtf(bd2) * INVH) + 1) : G;

            if (rq >= 8) {
                float ml = m;
                for (int v = lane; v < npts; v += 32) {
                    const float4 q = pts[v];
                    ml = fmaxf(ml, fmaf(px, q.x, fmaf(py, q.y, fmaf(pz, q.z, q.w))));
                }
                #pragma unroll
                for (int o = 16; o; o >>= 1)
                    ml = fmaxf(ml, __shfl_xor_sync(FULL, ml, o));
                m = ml;
            } else {
                const int z0 = max(cz - rq, 0), z1 = min(cz + rq, G - 1);
                const int y0 = max(cy - rq, 0), y1 = min(cy + rq, G - 1);
                const int x0 = max(cx - rq, 0), x1 = min(cx + rq, G - 1);
                const int ny = y1 - y0 + 1;
                const int nr = (z1 - z0 + 1) * ny;
                float ml = m;
                for (int ridx = lane; ridx < nr; ridx += 32) {
                    const int zz = z0 + ridx / ny;
                    const int yy = y0 + ridx % ny;
                    const int rb = (zz * G + yy) * G;
                    const int bb = st[rb + x0], ee = cu[rb + x1];
                    for (int v = bb; v < ee; v++) {
                        const float4 q = pts[v];
                        ml = fmaxf(ml, fmaf(px, q.x, fmaf(py, q.y, fmaf(pz, q.z, q.w))));
                    }
                }
                #pragma unroll
                for (int o = 16; o; o >>= 1)
                    ml = fmaxf(ml, __shfl_xor_sync(FULL, ml, o));
                m = ml;
            }
            bd2 = fmaf(-2.0f, m, p2);
        }

        if (lane == 0) acc += bd2 * scale;
    }

    if (lane == 0 && acc != 0.0f) atomicAdd(out, acc);
}

extern "C" void kernel_launch(void* const* d_in, const int* in_sizes, int n_in,
                              void* d_out, int out_size) {
    const float* pf = (const float*)d_in[0];
    const float* gf = (const float*)d_in[1];
    const float* pn = (const float*)d_in[2];
    const float* gn = (const float*)d_in[3];
    float* out = (float*)d_out;

    // g_cnt zeroed at module load and re-zeroed by k_scan every call.
    k_count<<<NQ_TOTAL / 256, 256>>>(pf, gf, pn, gn);     // launch 0
    k_scan<<<NSTRUCT, 1024>>>(out);                       // launch 1
    k_scatter<<<NQ_TOTAL / 256, 256>>>(pf, gf, pn, gn);   // launch 2
    k_query<<<QBLOCKS, QBLK>>>(out);                      // launch 3 (ncu slot)
    k_fixup<<<FIXBLOCKS, FIXBLK>>>(out);                  // launch 4
}